// round 8
// baseline (speedup 1.0000x reference)
#include <cuda_runtime.h>
#include <cuda_fp16.h>
#include <math.h>

// Problem constants
#define B_SZ   8
#define N_SZ   4096
#define E_SZ   131072
#define F_SZ   64
#define ALPHA  0.2f
#define CAP    128        // per-node bucket capacity (deg ~ Poisson(32))

#define GEMM_BLOCKS 256   // 128 rows per block
#define SCAT_BLOCKS 128   // E / (256*4)

// ---------------- scratch (device globals; no allocation allowed) ----------
// NOTE: zero-initialized at module load; k_main re-zeroes g_count each call.
__device__ __half2 g_Wh2[(size_t)B_SZ * N_SZ * 32];   // Wh in fp16, 4 MB
__device__ float   g_ssrc[B_SZ * N_SZ];
__device__ float   g_sdst[B_SZ * N_SZ];
__device__ int     g_count[N_SZ];
__device__ int2    g_edge[N_SZ * CAP];                // (dst, weight) by src

__device__ __forceinline__ unsigned cvt_tf32(float f) {
    unsigned u;
    asm("cvt.rna.tf32.f32 %0, %1;" : "=r"(u) : "f"(f));
    return u;
}

__device__ __forceinline__ void mma_tf32(float* d,
                                         unsigned a0, unsigned a1,
                                         unsigned a2, unsigned a3,
                                         unsigned b0, unsigned b1) {
    asm volatile(
        "mma.sync.aligned.m16n8k8.row.col.f32.tf32.tf32.f32 "
        "{%0,%1,%2,%3}, {%4,%5,%6,%7}, {%8,%9}, {%0,%1,%2,%3};"
        : "+f"(d[0]), "+f"(d[1]), "+f"(d[2]), "+f"(d[3])
        : "r"(a0), "r"(a1), "r"(a2), "r"(a3), "r"(b0), "r"(b1));
}

// ---------------- kernel 1 (fused): tf32-MMA GEMM + exact scores | scatter --
// Blocks [0, 256): Wh = h @ W (128-row tile) via m16n8k8 tf32 tensor mma;
//   scores computed EXACTLY in fp32 via s = h . (W @ a) re-association.
// Blocks [256, 384): bucketed edge scatter.
__global__ void __launch_bounds__(256) k_fused(const float* __restrict__ h,
                                               const float* __restrict__ W,
                                               const float* __restrict__ a,
                                               const int*   __restrict__ ei,
                                               const float* __restrict__ ew) {
    const int tid = threadIdx.x;

    if (blockIdx.x >= GEMM_BLOCKS) {
        // ---- scatter path: interleaved (dst, weight) 8B stores ----
        const int sc = blockIdx.x - GEMM_BLOCKS;
        const int v  = sc * 256 + tid;                 // vec4 index
        int4   s4 = ((const int4*)  ei)[v];
        int4   d4 = ((const int4*) (ei + E_SZ))[v];
        float4 w4 = ((const float4*)ew)[v];
#pragma unroll
        for (int j = 0; j < 4; j++) {
            int s = (&s4.x)[j];
            int p = atomicAdd(&g_count[s], 1);
            if (p < CAP)
                g_edge[s * CAP + p] = make_int2((&d4.x)[j],
                                                __float_as_int((&w4.x)[j]));
        }
        return;
    }

    // ---- GEMM path ----
    __shared__ float As[128][68];   // stride 68 -> conflict-free mma A-frags
    __shared__ float sA[128];
    __shared__ float sWa[128];      // Wa1 = W@a1 in [0,64), Wa2 in [64,128)

    const int row0 = blockIdx.x * 128;

    if (tid < 128) sA[tid] = a[tid];
#pragma unroll
    for (int j = 0; j < 8; j++) {
        int i = tid + j * 256;                 // 0..2047 float4s
        int r = i >> 4, c4 = i & 15;
        float4 v = ((const float4*)(h + (size_t)(row0 + r) * 64))[c4];
        *(float4*)&As[r][c4 * 4] = v;
    }
    __syncthreads();

    // Wa = W @ a1 / W @ a2 (exact fp32; W is L1-resident, 16KB)
    if (tid < 128) {
        const int which = tid >> 6;            // 0: a1, 1: a2
        const int i     = tid & 63;            // W row
        float s = 0.f;
#pragma unroll 8
        for (int f = 0; f < 64; f++)
            s += __ldg(&W[i * 64 + f]) * sA[which * 64 + f];
        sWa[tid] = s;
    }

    // ---- mma mainloop: warp w -> rows [w*16, w*16+16) of the tile ----
    const int wid  = tid >> 5, lane = tid & 31;
    const int gid  = lane >> 2, tig = lane & 3;
    const int wrow = wid * 16;
    float d[8][4];
#pragma unroll
    for (int nt = 0; nt < 8; nt++)
#pragma unroll
        for (int j = 0; j < 4; j++) d[nt][j] = 0.f;

#pragma unroll
    for (int kc = 0; kc < 8; kc++) {
        const int k0 = kc * 8;
        unsigned a0c = cvt_tf32(As[wrow + gid    ][k0 + tig    ]);
        unsigned a1c = cvt_tf32(As[wrow + gid + 8][k0 + tig    ]);
        unsigned a2c = cvt_tf32(As[wrow + gid    ][k0 + tig + 4]);
        unsigned a3c = cvt_tf32(As[wrow + gid + 8][k0 + tig + 4]);
#pragma unroll
        for (int nt = 0; nt < 8; nt++) {
            unsigned b0 = cvt_tf32(__ldg(&W[(k0 + tig    ) * 64 + nt * 8 + gid]));
            unsigned b1 = cvt_tf32(__ldg(&W[(k0 + tig + 4) * 64 + nt * 8 + gid]));
            mma_tf32(d[nt], a0c, a1c, a2c, a3c, b0, b1);
        }
    }
    __syncthreads();   // sWa ready; As still valid

    // ---- exact scores: thread t -> row t>>1, score t&1 ----
    {
        const int rt = tid >> 1, which = tid & 1;
        float s = 0.f;
#pragma unroll 8
        for (int f = 0; f < 64; f++)
            s += As[rt][f] * sWa[which * 64 + f];
        const int grow = row0 + rt;
        if (which == 0) g_ssrc[grow] = s;
        else            g_sdst[grow] = s;
    }

    // ---- store Wh fp16 from mma accumulators ----
#pragma unroll
    for (int nt = 0; nt < 8; nt++) {
        const int rg = row0 + wrow + gid;
        __half2 lo = __floats2half2_rn(d[nt][0], d[nt][1]);
        __half2 hi = __floats2half2_rn(d[nt][2], d[nt][3]);
        g_Wh2[(size_t)rg       * 32 + nt * 4 + tig] = lo;
        g_Wh2[(size_t)(rg + 8) * 32 + nt * 4 + tig] = hi;
    }
}

// ---------------- kernel 2: per-node softmax aggregation (R4-proven) -------
// One block per node n; warp b handles batch b.
// Pass A: p = exp(lrelu(ssrc+sdst)*w)  (no max pass; |e| small, no overflow).
// Pass B: 2 edges in flight, 16 lanes/edge, LDG.64 = 4 fp16 features/lane.
__global__ void __launch_bounds__(256) k_main(float* __restrict__ out) {
    const int n    = blockIdx.x;
    const int b    = threadIdx.x >> 5;
    const int lane = threadIdx.x & 31;

    __shared__ int2 s_dw[CAP];
    __shared__ int2 s_dp[B_SZ][CAP + 2];

    const int deg = min(g_count[n], CAP);   // read BEFORE reset

    for (int i = threadIdx.x; i < deg; i += 256)
        s_dw[i] = g_edge[n * CAP + i];
    __syncthreads();
    if (threadIdx.x == 0) g_count[n] = 0;   // reset for next graph replay

    const float ssrc = g_ssrc[b * N_SZ + n];
    const float* __restrict__ sd = &g_sdst[b * N_SZ];

    // ---- pass A: attention weights (lane-strided) ----
    float denom = 0.f;
    for (int k = lane; k < deg; k += 32) {
        int2  dw = s_dw[k];
        float e  = ssrc + __ldg(&sd[dw.x]);
        e = fmaxf(e, ALPHA * e) * __int_as_float(dw.y);   // leaky relu * w
        float p = __expf(e);
        denom += p;
        s_dp[b][k] = make_int2(dw.x * 128, __float_as_int(p));
    }
#pragma unroll
    for (int o = 16; o > 0; o >>= 1)
        denom += __shfl_xor_sync(0xffffffffu, denom, o);
    if (lane == 0) s_dp[b][deg] = make_int2(0, 0);        // pad for odd deg
    __syncwarp();

    // ---- pass B: 2 edges/iter, 16 lanes/edge, LDG.64 (4 halves)/lane ----
    const int  sub  = lane >> 4;            // 0: edge k, 1: edge k+1
    const char* base = (const char*)(g_Wh2 + (size_t)b * N_SZ * 32)
                     + (lane & 15) * 8;
    float a0 = 0.f, a1 = 0.f, a2 = 0.f, a3 = 0.f;
#pragma unroll 2
    for (int k = 0; k < deg; k += 2) {
        int2  dp = s_dp[b][k + sub];
        float p  = __int_as_float(dp.y);
        uint2 raw = *(const uint2*)(base + dp.x);         // LDG.64: 4 halves
        float2 f0 = __half22float2(*(const __half2*)&raw.x);
        float2 f1 = __half22float2(*(const __half2*)&raw.y);
        a0 += p * f0.x; a1 += p * f0.y;
        a2 += p * f1.x; a3 += p * f1.y;
    }
    // combine the two edge-subsets (lanes l and l+16 hold same features)
    a0 += __shfl_xor_sync(0xffffffffu, a0, 16);
    a1 += __shfl_xor_sync(0xffffffffu, a1, 16);
    a2 += __shfl_xor_sync(0xffffffffu, a2, 16);
    a3 += __shfl_xor_sync(0xffffffffu, a3, 16);

    if (lane < 16) {
        float r0 = 0.f, r1 = 0.f, r2 = 0.f, r3 = 0.f;
        if (deg > 0) {
            float inv = 1.f / denom;
            r0 = a0 * inv; r1 = a1 * inv; r2 = a2 * inv; r3 = a3 * inv;
        }
        r0 = r0 > 0.f ? r0 : expm1f(r0);
        r1 = r1 > 0.f ? r1 : expm1f(r1);
        r2 = r2 > 0.f ? r2 : expm1f(r2);
        r3 = r3 > 0.f ? r3 : expm1f(r3);
        *(float4*)&out[((size_t)b * N_SZ + n) * 64 + lane * 4]
            = make_float4(r0, r1, r2, r3);
    }
}

// ---------------- launch ---------------------------------------------------
extern "C" void kernel_launch(void* const* d_in, const int* in_sizes, int n_in,
                              void* d_out, int out_size) {
    const float* h  = (const float*)d_in[0];
    const int*   ei = (const int*)  d_in[1];
    const float* ew = (const float*)d_in[2];
    const float* W  = (const float*)d_in[3];
    const float* a  = (const float*)d_in[4];
    float* out = (float*)d_out;

    k_fused<<<GEMM_BLOCKS + SCAT_BLOCKS, 256>>>(h, W, a, ei, ew);
    k_main <<<N_SZ, 256>>>(out);
}

// round 9
// speedup vs baseline: 1.3013x; 1.3013x over previous
#include <cuda_runtime.h>
#include <cuda_fp16.h>
#include <math.h>

// Problem constants
#define B_SZ   8
#define N_SZ   4096
#define E_SZ   131072
#define F_SZ   64
#define ALPHA  0.2f
#define CAP    128        // per-node bucket capacity (deg ~ Poisson(32))

#define GEMM_BLOCKS 512
#define SCAT_BLOCKS 128   // E / (256*4)

// ---------------- scratch (device globals; no allocation allowed) ----------
// NOTE: zero-initialized at module load; k_main re-zeroes g_count each call.
__device__ __half2 g_Wh2[(size_t)B_SZ * N_SZ * 32];   // Wh in fp16, 4 MB
__device__ float   g_ssrc[B_SZ * N_SZ];
__device__ float   g_sdst[B_SZ * N_SZ];
__device__ int     g_count[N_SZ];
__device__ int2    g_edge[N_SZ * CAP];                // (dst, weight) by src

// ---------------- kernel 1 (fused): GEMM+scores  |  edge scatter -----------
__global__ void __launch_bounds__(256) k_fused(const float* __restrict__ h,
                                               const float* __restrict__ W,
                                               const float* __restrict__ a,
                                               const int*   __restrict__ ei,
                                               const float* __restrict__ ew) {
    const int tid = threadIdx.x;

    if (blockIdx.x >= GEMM_BLOCKS) {
        // ---- scatter path: interleaved (dst, weight) 8B stores ----
        const int sc = blockIdx.x - GEMM_BLOCKS;
        const int v  = sc * 256 + tid;                 // vec4 index
        int4   s4 = ((const int4*)  ei)[v];
        int4   d4 = ((const int4*) (ei + E_SZ))[v];
        float4 w4 = ((const float4*)ew)[v];
#pragma unroll
        for (int j = 0; j < 4; j++) {
            int s = (&s4.x)[j];
            int p = atomicAdd(&g_count[s], 1);
            if (p < CAP)
                g_edge[s * CAP + p] = make_int2((&d4.x)[j],
                                                __float_as_int((&w4.x)[j]));
        }
        return;
    }

    // ---- GEMM path: Wh = h @ W (64-row tile), scores epilogue ----
    __shared__ float As[64][68];     // stride 68: float4-aligned k-chunks
    __shared__ float Ws[64][64];
    __shared__ float sA[128];
    const int row0 = blockIdx.x * 64;

    if (tid < 128) sA[tid] = a[tid];
    for (int i = tid; i < 1024; i += 256)
        ((float4*)Ws)[i] = ((const float4*)W)[i];
    for (int i = tid; i < 1024; i += 256) {
        int r = i >> 4, f4 = i & 15;
        float4 v = ((const float4*)(h + (size_t)(row0 + r) * 64))[f4];
        *(float4*)&As[r][f4 * 4] = v;
    }
    __syncthreads();

    const int tx = tid & 15, ty = tid >> 4;   // 16x16 threads, 4x4 microtile
    float acc[4][4];
#pragma unroll
    for (int i = 0; i < 4; i++)
#pragma unroll
        for (int j = 0; j < 4; j++) acc[i][j] = 0.f;

#pragma unroll
    for (int k0 = 0; k0 < 64; k0 += 4) {
        float4 a4[4];
#pragma unroll
        for (int i = 0; i < 4; i++)
            a4[i] = *(const float4*)&As[ty * 4 + i][k0];   // broadcast LDS.128
#pragma unroll
        for (int kk = 0; kk < 4; kk++) {
            float4 bv = *(const float4*)&Ws[k0 + kk][tx * 4];
#pragma unroll
            for (int i = 0; i < 4; i++) {
                float av = (&a4[i].x)[kk];
                acc[i][0] += av * bv.x;
                acc[i][1] += av * bv.y;
                acc[i][2] += av * bv.z;
                acc[i][3] += av * bv.w;
            }
        }
    }

#pragma unroll
    for (int i = 0; i < 4; i++) {
        const int row = row0 + ty * 4 + i;
        __half2 h0 = __floats2half2_rn(acc[i][0], acc[i][1]);
        __half2 h1 = __floats2half2_rn(acc[i][2], acc[i][3]);
        g_Wh2[(size_t)row * 32 + tx * 2 + 0] = h0;
        g_Wh2[(size_t)row * 32 + tx * 2 + 1] = h1;

        float s1 = acc[i][0] * sA[tx * 4 + 0] + acc[i][1] * sA[tx * 4 + 1]
                 + acc[i][2] * sA[tx * 4 + 2] + acc[i][3] * sA[tx * 4 + 3];
        float s2 = acc[i][0] * sA[64 + tx * 4 + 0] + acc[i][1] * sA[64 + tx * 4 + 1]
                 + acc[i][2] * sA[64 + tx * 4 + 2] + acc[i][3] * sA[64 + tx * 4 + 3];
#pragma unroll
        for (int o = 8; o > 0; o >>= 1) {
            s1 += __shfl_xor_sync(0xffffffffu, s1, o);
            s2 += __shfl_xor_sync(0xffffffffu, s2, o);
        }
        if (tx == 0) { g_ssrc[row] = s1; g_sdst[row] = s2; }
    }
}

// ---------------- kernel 2: per-node softmax aggregation -------------------
// One block per node n; warp b handles batch b.
// Pass A: p = exp(lrelu(ssrc+sdst)*w)  (no max pass; |e| small, no overflow).
// Pass B: 8 edges per iteration, 4 LDG.64s in flight (MLP=4), two
//         accumulator chains. s_dp padded with 8 zero entries -> no tail loop.
__global__ void __launch_bounds__(256) k_main(float* __restrict__ out) {
    const int n    = blockIdx.x;
    const int b    = threadIdx.x >> 5;
    const int lane = threadIdx.x & 31;

    __shared__ int2 s_dw[CAP];
    __shared__ int2 s_dp[B_SZ][CAP + 8];

    const int deg = min(g_count[n], CAP);   // read BEFORE reset

    for (int i = threadIdx.x; i < deg; i += 256)
        s_dw[i] = g_edge[n * CAP + i];
    __syncthreads();
    if (threadIdx.x == 0) g_count[n] = 0;   // reset for next graph replay

    const float ssrc = g_ssrc[b * N_SZ + n];
    const float* __restrict__ sd = &g_sdst[b * N_SZ];

    // ---- pass A: attention weights (lane-strided) ----
    float denom = 0.f;
    for (int k = lane; k < deg; k += 32) {
        int2  dw = s_dw[k];
        float e  = ssrc + __ldg(&sd[dw.x]);
        e = fmaxf(e, ALPHA * e) * __int_as_float(dw.y);   // leaky relu * w
        float p = __expf(e);
        denom += p;
        s_dp[b][k] = make_int2(dw.x * 128, __float_as_int(p));
    }
#pragma unroll
    for (int o = 16; o > 0; o >>= 1)
        denom += __shfl_xor_sync(0xffffffffu, denom, o);
    if (lane < 8) s_dp[b][deg + lane] = make_int2(0, 0);  // pad: no tail loop
    __syncwarp();

    // ---- pass B: 8 edges/iter, 16 lanes/edge, 4x LDG.64 in flight ----
    const int  sub  = lane >> 4;            // 0: even edge, 1: odd edge
    const char* base = (const char*)(g_Wh2 + (size_t)b * N_SZ * 32)
                     + (lane & 15) * 8;     // 8B fp16 feature slice
    float a0 = 0.f, a1 = 0.f, a2 = 0.f, a3 = 0.f;
    float c0 = 0.f, c1 = 0.f, c2 = 0.f, c3 = 0.f;
    for (int k = 0; k < deg; k += 8) {
        int2 dp0 = s_dp[b][k     + sub];
        int2 dp1 = s_dp[b][k + 2 + sub];
        int2 dp2 = s_dp[b][k + 4 + sub];
        int2 dp3 = s_dp[b][k + 6 + sub];
        uint2 r0 = *(const uint2*)(base + dp0.x);   // 4 independent LDG.64s
        uint2 r1 = *(const uint2*)(base + dp1.x);
        uint2 r2 = *(const uint2*)(base + dp2.x);
        uint2 r3 = *(const uint2*)(base + dp3.x);

        float p0 = __int_as_float(dp0.y);
        float2 f00 = __half22float2(*(const __half2*)&r0.x);
        float2 f01 = __half22float2(*(const __half2*)&r0.y);
        a0 += p0 * f00.x; a1 += p0 * f00.y;
        a2 += p0 * f01.x; a3 += p0 * f01.y;

        float p1 = __int_as_float(dp1.y);
        float2 f10 = __half22float2(*(const __half2*)&r1.x);
        float2 f11 = __half22float2(*(const __half2*)&r1.y);
        c0 += p1 * f10.x; c1 += p1 * f10.y;
        c2 += p1 * f11.x; c3 += p1 * f11.y;

        float p2 = __int_as_float(dp2.y);
        float2 f20 = __half22float2(*(const __half2*)&r2.x);
        float2 f21 = __half22float2(*(const __half2*)&r2.y);
        a0 += p2 * f20.x; a1 += p2 * f20.y;
        a2 += p2 * f21.x; a3 += p2 * f21.y;

        float p3 = __int_as_float(dp3.y);
        float2 f30 = __half22float2(*(const __half2*)&r3.x);
        float2 f31 = __half22float2(*(const __half2*)&r3.y);
        c0 += p3 * f30.x; c1 += p3 * f30.y;
        c2 += p3 * f31.x; c3 += p3 * f31.y;
    }
    a0 += c0; a1 += c1; a2 += c2; a3 += c3;

    // combine the two edge-subsets (lanes l and l+16 hold same features)
    a0 += __shfl_xor_sync(0xffffffffu, a0, 16);
    a1 += __shfl_xor_sync(0xffffffffu, a1, 16);
    a2 += __shfl_xor_sync(0xffffffffu, a2, 16);
    a3 += __shfl_xor_sync(0xffffffffu, a3, 16);

    if (lane < 16) {
        float r0 = 0.f, r1 = 0.f, r2 = 0.f, r3 = 0.f;
        if (deg > 0) {
            float inv = 1.f / denom;
            r0 = a0 * inv; r1 = a1 * inv; r2 = a2 * inv; r3 = a3 * inv;
        }
        // ELU tail: expm1f(x) == __expf(x)-1 to ~6e-8 abs near 0; much cheaper
        r0 = r0 > 0.f ? r0 : __expf(r0) - 1.f;
        r1 = r1 > 0.f ? r1 : __expf(r1) - 1.f;
        r2 = r2 > 0.f ? r2 : __expf(r2) - 1.f;
        r3 = r3 > 0.f ? r3 : __expf(r3) - 1.f;
        *(float4*)&out[((size_t)b * N_SZ + n) * 64 + lane * 4]
            = make_float4(r0, r1, r2, r3);
    }
}

// ---------------- launch ---------------------------------------------------
extern "C" void kernel_launch(void* const* d_in, const int* in_sizes, int n_in,
                              void* d_out, int out_size) {
    const float* h  = (const float*)d_in[0];
    const int*   ei = (const int*)  d_in[1];
    const float* ew = (const float*)d_in[2];
    const float* W  = (const float*)d_in[3];
    const float* a  = (const float*)d_in[4];
    float* out = (float*)d_out;

    k_fused<<<GEMM_BLOCKS + SCAT_BLOCKS, 256>>>(h, W, a, ei, ew);
    k_main <<<N_SZ, 256>>>(out);
}